// round 1
// baseline (speedup 1.0000x reference)
#include <cuda_runtime.h>
#include <cstdint>
#include <cstdio>

// ---------------- static device scratch (no allocations allowed) ----------------
#define MAXN 131072
#define MAXE 2000000

__device__ int    g_flag64;
__device__ int    g_src[MAXE];
__device__ int    g_dst[MAXE];
__device__ float  g_norm[MAXE];
__device__ int    g_deg[MAXN];
__device__ float  g_dinv[MAXN];
__device__ float  g_dinv2[MAXN];
__device__ float  g_bufA[(size_t)MAXN * 96];
__device__ float  g_bufB[(size_t)MAXN * 96];
__device__ double g_sum[96];
__device__ double g_sumsq[96];
__device__ float  g_scale[96];
__device__ float  g_shift[96];

// ---------------- edge-index dtype detection ----------------
// If the edge tensor is int64, every odd 32-bit word (high half of a value
// < 2^31) is zero. For int32 data the odd words are random indices in [0,N):
// the chance 256 of them are all zero is ~(2e-5)^256.
__global__ void k_detect(const int* __restrict__ p) {
    int v = p[2 * threadIdx.x + 1];
    unsigned any = __ballot_sync(0xffffffffu, v != 0);
    __shared__ int s;
    if (threadIdx.x == 0) s = 0;
    __syncthreads();
    if (any && (threadIdx.x % 32 == 0)) atomicOr(&s, 1);
    __syncthreads();
    if (threadIdx.x == 0) g_flag64 = (s == 0) ? 1 : 0;
}

__global__ void k_deginit(int N) {
    int i = blockIdx.x * blockDim.x + threadIdx.x;
    if (i < N) g_deg[i] = 1;  // self-loop
}

__global__ void k_convert(const int* __restrict__ p, int E) {
    int e = blockIdx.x * blockDim.x + threadIdx.x;
    if (e >= E) return;
    int s, d;
    if (g_flag64) { s = p[2 * e]; d = p[2 * (E + e)]; }
    else          { s = p[e];     d = p[E + e]; }
    g_src[e] = s;
    g_dst[e] = d;
    atomicAdd(&g_deg[d], 1);
}

__global__ void k_dinv(int N) {
    int i = blockIdx.x * blockDim.x + threadIdx.x;
    if (i >= N) return;
    float dg = (float)g_deg[i];
    float di = rsqrtf(dg);
    g_dinv[i]  = di;
    g_dinv2[i] = 1.0f / dg;
}

__global__ void k_norm(int E) {
    int e = blockIdx.x * blockDim.x + threadIdx.x;
    if (e >= E) return;
    g_norm[e] = g_dinv[g_src[e]] * g_dinv[g_dst[e]];
}

// ---------------- aggregation ----------------
// agg[i] = h[i] * dinv2[i]   (self-loop contribution, also zero-initializes)
__global__ void k_selfloop(const float* __restrict__ in, float* __restrict__ out,
                           int N, int F) {
    int t = blockIdx.x * blockDim.x + threadIdx.x;
    if (t >= N * F) return;
    int i = t / F;
    out[t] = in[t] * g_dinv2[i];
}

// one thread per (edge, float4-chunk); v4 reduction into L2
__global__ void k_edge_agg(const float* __restrict__ h, float* __restrict__ agg,
                           int E, int C /* = F/4 */) {
    int t = blockIdx.x * blockDim.x + threadIdx.x;
    int total = E * C;
    if (t >= total) return;
    int e = t / C;
    int c = t - e * C;
    int s = g_src[e], d = g_dst[e];
    float nrm = g_norm[e];
    float4 v = __ldg((const float4*)h + (size_t)s * C + c);
    float4* ap = (float4*)agg + (size_t)d * C + c;
    asm volatile("red.global.add.v4.f32 [%0], {%1,%2,%3,%4};"
                 :: "l"(ap), "f"(v.x * nrm), "f"(v.y * nrm),
                    "f"(v.z * nrm), "f"(v.w * nrm)
                 : "memory");
}

// width-2 variant for the final layer
__global__ void k_edge_agg2(const float* __restrict__ h, float* __restrict__ out, int E) {
    int e = blockIdx.x * blockDim.x + threadIdx.x;
    if (e >= E) return;
    int s = g_src[e], d = g_dst[e];
    float nrm = g_norm[e];
    float2 v = __ldg((const float2*)h + s);
    float2* ap = (float2*)out + d;
    asm volatile("red.global.add.v2.f32 [%0], {%1,%2};"
                 :: "l"(ap), "f"(v.x * nrm), "f"(v.y * nrm)
                 : "memory");
}

// ---------------- GEMM: Y[N,96] = X[N,Fi] @ W[Fi,96] + b ----------------
// block (16,16): 32 rows/block (2 rows/thread), 6 output cols/thread
__global__ __launch_bounds__(256) void k_gemm96(
    const float* __restrict__ X, const float* __restrict__ W,
    const float* __restrict__ b, float* __restrict__ Y, int N, int Fi) {
    __shared__ float Ws[96 * 96];
    __shared__ float Xs[32 * 96];
    int tid = threadIdx.y * 16 + threadIdx.x;
    for (int i = tid; i < Fi * 96; i += 256) Ws[i] = W[i];
    int row0 = blockIdx.x * 32;
    for (int i = tid; i < 32 * Fi; i += 256) {
        int r = i / Fi, k = i - r * Fi;
        Xs[i] = (row0 + r < N) ? X[(size_t)(row0 + r) * Fi + k] : 0.0f;
    }
    __syncthreads();
    float acc0[6] = {0, 0, 0, 0, 0, 0};
    float acc1[6] = {0, 0, 0, 0, 0, 0};
    int cb = threadIdx.x * 6;
    const float* xs0 = &Xs[threadIdx.y * Fi];
    const float* xs1 = &Xs[(threadIdx.y + 16) * Fi];
    #pragma unroll 4
    for (int k = 0; k < Fi; k++) {
        float a0 = xs0[k], a1 = xs1[k];
        #pragma unroll
        for (int j = 0; j < 6; j++) {
            float w = Ws[k * 96 + cb + j];
            acc0[j] += a0 * w;
            acc1[j] += a1 * w;
        }
    }
    int r0 = row0 + threadIdx.y, r1 = r0 + 16;
    if (r0 < N) {
        #pragma unroll
        for (int j = 0; j < 6; j++) Y[(size_t)r0 * 96 + cb + j] = acc0[j] + b[cb + j];
    }
    if (r1 < N) {
        #pragma unroll
        for (int j = 0; j < 6; j++) Y[(size_t)r1 * 96 + cb + j] = acc1[j] + b[cb + j];
    }
}

// ---------------- final projection: T[N,2] = X[N,96] @ W[96,2] ----------------
__global__ __launch_bounds__(256) void k_gemm_out(
    const float* __restrict__ X, const float* __restrict__ W,
    float* __restrict__ T, int N) {
    __shared__ float Ws[192];
    int tid = threadIdx.x;
    if (tid < 192) Ws[tid] = W[tid];
    __syncthreads();
    int warp = tid / 32, lane = tid % 32;
    int row = blockIdx.x * 8 + warp;
    if (row >= N) return;
    float s0 = 0.0f, s1 = 0.0f;
    #pragma unroll
    for (int k0 = 0; k0 < 96; k0 += 32) {
        float x = X[(size_t)row * 96 + k0 + lane];
        s0 += x * Ws[(k0 + lane) * 2];
        s1 += x * Ws[(k0 + lane) * 2 + 1];
    }
    #pragma unroll
    for (int o = 16; o; o >>= 1) {
        s0 += __shfl_down_sync(0xffffffffu, s0, o);
        s1 += __shfl_down_sync(0xffffffffu, s1, o);
    }
    if (lane == 0) { T[(size_t)row * 2] = s0; T[(size_t)row * 2 + 1] = s1; }
}

// out[i,j] = b[j] + T[i,j] * dinv2[i]
__global__ void k_outinit(const float* __restrict__ T, const float* __restrict__ b,
                          float* __restrict__ out, int N) {
    int t = blockIdx.x * blockDim.x + threadIdx.x;
    if (t >= N * 2) return;
    int i = t >> 1, j = t & 1;
    out[t] = b[j] + T[t] * g_dinv2[i];
}

// ---------------- BatchNorm ----------------
__global__ void k_zstats() {
    int c = threadIdx.x;
    if (c < 96) { g_sum[c] = 0.0; g_sumsq[c] = 0.0; }
}

__global__ void k_stats(const float* __restrict__ X, int N) {
    int c = threadIdx.x;  // 96 threads
    double s = 0.0, sq = 0.0;
    for (int r = blockIdx.x; r < N; r += gridDim.x) {
        double v = (double)X[(size_t)r * 96 + c];
        s += v; sq += v * v;
    }
    atomicAdd(&g_sum[c], s);
    atomicAdd(&g_sumsq[c], sq);
}

__global__ void k_bnfin(const float* __restrict__ g, const float* __restrict__ be, int N) {
    int c = threadIdx.x;
    if (c >= 96) return;
    double mu  = g_sum[c] / (double)N;
    double var = g_sumsq[c] / (double)N - mu * mu;
    if (var < 0.0) var = 0.0;
    float a = g[c] * rsqrtf((float)var + 1e-5f);
    g_scale[c] = a;
    g_shift[c] = be[c] - (float)mu * a;
}

__global__ void k_bnrelu(const float* __restrict__ X, float* __restrict__ Y, int total) {
    int t = blockIdx.x * blockDim.x + threadIdx.x;
    if (t >= total) return;
    int c = t % 96;
    float v = X[t] * g_scale[c] + g_shift[c];
    Y[t] = v > 0.0f ? v : 0.0f;
}

// ---------------- host ----------------
static inline int cdiv(int a, int b) { return (a + b - 1) / b; }

extern "C" void kernel_launch(void* const* d_in, const int* in_sizes, int n_in,
                              void* d_out, int out_size) {
    const float* x  = (const float*)d_in[0];
    const int*   ei = (const int*)d_in[1];
    const float* W1 = (const float*)d_in[2];  const float* b1 = (const float*)d_in[3];
    const float* g1 = (const float*)d_in[4];  const float* be1 = (const float*)d_in[5];
    const float* W2 = (const float*)d_in[6];  const float* b2 = (const float*)d_in[7];
    const float* g2 = (const float*)d_in[8];  const float* be2 = (const float*)d_in[9];
    const float* W3 = (const float*)d_in[10]; const float* b3 = (const float*)d_in[11];
    const float* g3 = (const float*)d_in[12]; const float* be3 = (const float*)d_in[13];
    const float* W4 = (const float*)d_in[14]; const float* b4 = (const float*)d_in[15];
    float* out = (float*)d_out;

    int E    = in_sizes[1] / 2;
    int H    = in_sizes[3];            // 96
    int Fin  = in_sizes[2] / H;        // 32
    int N    = in_sizes[0] / Fin;      // 50000
    (void)n_in; (void)out_size;

    void *pA = nullptr, *pB = nullptr;
    cudaGetSymbolAddress(&pA, g_bufA);
    cudaGetSymbolAddress(&pB, g_bufB);
    float* bufA = (float*)pA;
    float* bufB = (float*)pB;

    // graph preprocessing
    k_detect<<<1, 256>>>(ei);
    k_deginit<<<cdiv(N, 256), 256>>>(N);
    k_convert<<<cdiv(E, 256), 256>>>(ei, E);
    k_dinv<<<cdiv(N, 256), 256>>>(N);
    k_norm<<<cdiv(E, 256), 256>>>(E);

    dim3 gblk(16, 16);

    // -------- layer 1: aggregate x (width 32) then transform --------
    k_selfloop<<<cdiv(N * Fin, 256), 256>>>(x, bufA, N, Fin);
    k_edge_agg<<<cdiv(E * (Fin / 4), 256), 256>>>(x, bufA, E, Fin / 4);
    k_gemm96<<<cdiv(N, 32), gblk>>>(bufA, W1, b1, bufB, N, Fin);
    k_zstats<<<1, 96>>>();
    k_stats<<<256, 96>>>(bufB, N);
    k_bnfin<<<1, 96>>>(g1, be1, N);
    k_bnrelu<<<cdiv(N * 96, 256), 256>>>(bufB, bufA, N * 96);

    // -------- layer 2 --------
    k_selfloop<<<cdiv(N * 96, 256), 256>>>(bufA, bufB, N, 96);
    k_edge_agg<<<cdiv(E * 24, 256), 256>>>(bufA, bufB, E, 24);
    k_gemm96<<<cdiv(N, 32), gblk>>>(bufB, W2, b2, bufA, N, 96);
    k_zstats<<<1, 96>>>();
    k_stats<<<256, 96>>>(bufA, N);
    k_bnfin<<<1, 96>>>(g2, be2, N);
    k_bnrelu<<<cdiv(N * 96, 256), 256>>>(bufA, bufA, N * 96);

    // -------- layer 3 --------
    k_selfloop<<<cdiv(N * 96, 256), 256>>>(bufA, bufB, N, 96);
    k_edge_agg<<<cdiv(E * 24, 256), 256>>>(bufA, bufB, E, 24);
    k_gemm96<<<cdiv(N, 32), gblk>>>(bufB, W3, b3, bufA, N, 96);
    k_zstats<<<1, 96>>>();
    k_stats<<<256, 96>>>(bufA, N);
    k_bnfin<<<1, 96>>>(g3, be3, N);
    k_bnrelu<<<cdiv(N * 96, 256), 256>>>(bufA, bufA, N * 96);

    // -------- layer 4: transform first (96 -> 2), then aggregate width 2 --------
    k_gemm_out<<<cdiv(N, 8), 256>>>(bufA, W4, bufB, N);
    k_outinit<<<cdiv(N * 2, 256), 256>>>(bufB, b4, out, N);
    k_edge_agg2<<<cdiv(E, 256), 256>>>(bufB, out, E);
}

// round 2
// speedup vs baseline: 1.5178x; 1.5178x over previous
#include <cuda_runtime.h>
#include <cstdint>

// ---------------- static device scratch ----------------
#define MAXN 131072
#define MAXE 2000000

__device__ int    g_flag64;
__device__ int    g_deg[MAXN];
__device__ float  g_dinv[MAXN];
__device__ float  g_dinv2[MAXN];
__device__ int    g_offs[MAXN + 1];
__device__ int    g_cursor[MAXN];
__device__ int    g_bsum[MAXN / 256 + 2];
__device__ int    g_bpre[MAXN / 256 + 2];
__device__ int2   g_csr[MAXE];          // (src, norm-as-int)
__device__ float  g_bufA[(size_t)MAXN * 96];
__device__ float  g_bufB[(size_t)MAXN * 96];
__device__ double g_sum[96];
__device__ double g_sumsq[96];
__device__ float  g_scale[96];
__device__ float  g_shift[96];

// ---------------- edge dtype detection (int64 vs int32) ----------------
__global__ void k_detect(const int* __restrict__ p) {
    int v = p[2 * threadIdx.x + 1];
    unsigned any = __ballot_sync(0xffffffffu, v != 0);
    __shared__ int s;
    if (threadIdx.x == 0) s = 0;
    __syncthreads();
    if (any && (threadIdx.x % 32 == 0)) atomicOr(&s, 1);
    __syncthreads();
    if (threadIdx.x == 0) g_flag64 = (s == 0) ? 1 : 0;
}

__global__ void k_zerodeg(int N) {
    int i = blockIdx.x * blockDim.x + threadIdx.x;
    if (i < N) g_deg[i] = 0;
}

__global__ void k_count(const int* __restrict__ p, int E) {
    int e = blockIdx.x * blockDim.x + threadIdx.x;
    if (e >= E) return;
    int d = g_flag64 ? p[2 * (E + e)] : p[E + e];
    atomicAdd(&g_deg[d], 1);
}

__global__ void k_dinv(int N) {
    int i = blockIdx.x * blockDim.x + threadIdx.x;
    if (i >= N) return;
    float dt = (float)(g_deg[i] + 1);   // +1 self-loop
    g_dinv[i]  = rsqrtf(dt);
    g_dinv2[i] = 1.0f / dt;
}

// ---------------- two-level exclusive scan of g_deg -> g_offs ----------------
__global__ void k_bsum(int N) {
    __shared__ int sh[256];
    int t = threadIdx.x;
    int i = blockIdx.x * 256 + t;
    sh[t] = (i < N) ? g_deg[i] : 0;
    __syncthreads();
    for (int s = 128; s; s >>= 1) {
        if (t < s) sh[t] += sh[t + s];
        __syncthreads();
    }
    if (t == 0) g_bsum[blockIdx.x] = sh[0];
}

__global__ void k_bscan(int nb) {   // single block, 512 threads
    __shared__ int sh[512];
    int t = threadIdx.x;
    int v = (t < nb) ? g_bsum[t] : 0;
    sh[t] = v;
    __syncthreads();
    for (int o = 1; o < 512; o <<= 1) {
        int x = (t >= o) ? sh[t - o] : 0;
        __syncthreads();
        sh[t] += x;
        __syncthreads();
    }
    if (t < nb) g_bpre[t] = sh[t] - v;  // exclusive
}

__global__ void k_offsets(int N) {
    __shared__ int sh[256];
    int t = threadIdx.x;
    int i = blockIdx.x * 256 + t;
    int v = (i < N) ? g_deg[i] : 0;
    sh[t] = v;
    __syncthreads();
    for (int o = 1; o < 256; o <<= 1) {
        int x = (t >= o) ? sh[t - o] : 0;
        __syncthreads();
        sh[t] += x;
        __syncthreads();
    }
    if (i < N) {
        int off = g_bpre[blockIdx.x] + sh[t] - v;
        g_offs[i]   = off;
        g_cursor[i] = off;
        if (i == N - 1) g_offs[N] = off + v;
    }
}

__global__ void k_scatter(const int* __restrict__ p, int E) {
    int e = blockIdx.x * blockDim.x + threadIdx.x;
    if (e >= E) return;
    int s, d;
    if (g_flag64) { s = p[2 * e]; d = p[2 * (E + e)]; }
    else          { s = p[e];     d = p[E + e]; }
    int pos = atomicAdd(&g_cursor[d], 1);
    g_csr[pos] = make_int2(s, __float_as_int(g_dinv[s] * g_dinv[d]));
}

// ---------------- CSR gather aggregation (warp per node) ----------------
// NL = F/4 lanes active (float4 each). If BN: input h is raw GEMM output,
// apply relu(h*scale+shift) on every gathered value (and the self term).
template<int NL, bool BN>
__global__ __launch_bounds__(256) void k_agg(
    const float* __restrict__ h, float* __restrict__ out, int N) {
    int gw   = (blockIdx.x * blockDim.x + threadIdx.x) >> 5;
    int lane = threadIdx.x & 31;
    if (gw >= N) return;
    const float4* hp = (const float4*)h;
    bool act = lane < NL;
    float4 sc = make_float4(0, 0, 0, 0), sf = make_float4(0, 0, 0, 0);
    float4 acc = make_float4(0, 0, 0, 0);
    if (act) {
        if (BN) {
            sc = ((const float4*)g_scale)[lane];
            sf = ((const float4*)g_shift)[lane];
        }
        float4 v = __ldg(hp + (size_t)gw * NL + lane);
        if (BN) {
            v.x = fmaxf(fmaf(v.x, sc.x, sf.x), 0.f);
            v.y = fmaxf(fmaf(v.y, sc.y, sf.y), 0.f);
            v.z = fmaxf(fmaf(v.z, sc.z, sf.z), 0.f);
            v.w = fmaxf(fmaf(v.w, sc.w, sf.w), 0.f);
        }
        float w = g_dinv2[gw];
        acc = make_float4(v.x * w, v.y * w, v.z * w, v.w * w);
    }
    int beg = g_offs[gw], end = g_offs[gw + 1];
    for (int e0 = beg; e0 < end; e0 += 32) {
        int e = e0 + lane;
        int2 ed = (e < end) ? g_csr[e] : make_int2(0, 0);
        int m = end - e0; if (m > 32) m = 32;
        for (int j = 0; j < m; j++) {
            int   s  = __shfl_sync(0xffffffffu, ed.x, j);
            float nm = __int_as_float(__shfl_sync(0xffffffffu, ed.y, j));
            if (act) {
                float4 v = __ldg(hp + (size_t)s * NL + lane);
                if (BN) {
                    v.x = fmaxf(fmaf(v.x, sc.x, sf.x), 0.f);
                    v.y = fmaxf(fmaf(v.y, sc.y, sf.y), 0.f);
                    v.z = fmaxf(fmaf(v.z, sc.z, sf.z), 0.f);
                    v.w = fmaxf(fmaf(v.w, sc.w, sf.w), 0.f);
                }
                acc.x = fmaf(nm, v.x, acc.x);
                acc.y = fmaf(nm, v.y, acc.y);
                acc.z = fmaf(nm, v.z, acc.z);
                acc.w = fmaf(nm, v.w, acc.w);
            }
        }
    }
    if (act) ((float4*)out)[(size_t)gw * NL + lane] = acc;
}

// ---------------- GEMM: Y[N,96] = X[N,Fi] @ W[Fi,96] + b, fused BN stats ----------------
__global__ __launch_bounds__(256) void k_gemm96(
    const float* __restrict__ X, const float* __restrict__ W,
    const float* __restrict__ b, float* __restrict__ Y, int N, int Fi) {
    __shared__ float Ws[96 * 96];
    __shared__ float Xs[32 * 96];   // reused as 16x100 reduction buffer later
    int tx = threadIdx.x, ty = threadIdx.y;
    int tid = ty * 16 + tx;
    for (int i = tid; i < Fi * 96; i += 256) Ws[i] = W[i];
    int row0 = blockIdx.x * 32;
    for (int i = tid; i < 32 * Fi; i += 256) {
        int r = i / Fi, k = i - r * Fi;
        Xs[i] = (row0 + r < N) ? X[(size_t)(row0 + r) * Fi + k] : 0.0f;
    }
    __syncthreads();
    float acc0[6] = {0, 0, 0, 0, 0, 0};
    float acc1[6] = {0, 0, 0, 0, 0, 0};
    int cb = tx * 6;
    const float* xs0 = &Xs[ty * Fi];
    const float* xs1 = &Xs[(ty + 16) * Fi];
    #pragma unroll 4
    for (int k = 0; k < Fi; k++) {
        float a0 = xs0[k], a1 = xs1[k];
        #pragma unroll
        for (int j = 0; j < 6; j++) {
            float w = Ws[k * 96 + cb + j];
            acc0[j] += a0 * w;
            acc1[j] += a1 * w;
        }
    }
    float bb[6];
    #pragma unroll
    for (int j = 0; j < 6; j++) bb[j] = b[cb + j];
    int r0 = row0 + ty, r1 = r0 + 16;
    float ls[6] = {0, 0, 0, 0, 0, 0}, lq[6] = {0, 0, 0, 0, 0, 0};
    if (r0 < N) {
        #pragma unroll
        for (int j = 0; j < 6; j++) {
            float v = acc0[j] + bb[j];
            Y[(size_t)r0 * 96 + cb + j] = v;
            ls[j] += v; lq[j] += v * v;
        }
    }
    if (r1 < N) {
        #pragma unroll
        for (int j = 0; j < 6; j++) {
            float v = acc1[j] + bb[j];
            Y[(size_t)r1 * 96 + cb + j] = v;
            ls[j] += v; lq[j] += v * v;
        }
    }
    // block reduction of per-column sums (reuse Xs, stride 100 to dodge conflicts)
    __syncthreads();
    float* sr = Xs;
    #pragma unroll
    for (int j = 0; j < 6; j++) sr[ty * 100 + cb + j] = ls[j];
    __syncthreads();
    for (int st = 8; st; st >>= 1) {
        if (ty < st)
            #pragma unroll
            for (int j = 0; j < 6; j++)
                sr[ty * 100 + cb + j] += sr[(ty + st) * 100 + cb + j];
        __syncthreads();
    }
    if (ty == 0)
        #pragma unroll
        for (int j = 0; j < 6; j++) atomicAdd(&g_sum[cb + j], (double)sr[cb + j]);
    __syncthreads();
    #pragma unroll
    for (int j = 0; j < 6; j++) sr[ty * 100 + cb + j] = lq[j];
    __syncthreads();
    for (int st = 8; st; st >>= 1) {
        if (ty < st)
            #pragma unroll
            for (int j = 0; j < 6; j++)
                sr[ty * 100 + cb + j] += sr[(ty + st) * 100 + cb + j];
        __syncthreads();
    }
    if (ty == 0)
        #pragma unroll
        for (int j = 0; j < 6; j++) atomicAdd(&g_sumsq[cb + j], (double)sr[cb + j]);
}

__global__ void k_zstats() {
    int c = threadIdx.x;
    if (c < 96) { g_sum[c] = 0.0; g_sumsq[c] = 0.0; }
}

__global__ void k_bnfin(const float* __restrict__ g, const float* __restrict__ be, int N) {
    int c = threadIdx.x;
    if (c >= 96) return;
    double mu  = g_sum[c] / (double)N;
    double var = g_sumsq[c] / (double)N - mu * mu;
    if (var < 0.0) var = 0.0;
    float a = g[c] * rsqrtf((float)var + 1e-5f);
    g_scale[c] = a;
    g_shift[c] = be[c] - (float)mu * a;
}

// ---------------- final projection with fused BN3+ReLU: T[N,2] ----------------
__global__ __launch_bounds__(256) void k_gemm_out(
    const float* __restrict__ X, const float* __restrict__ W,
    float* __restrict__ T, int N) {
    __shared__ float Ws[192];
    int tid = threadIdx.x;
    if (tid < 192) Ws[tid] = W[tid];
    __syncthreads();
    int warp = tid / 32, lane = tid % 32;
    int row = blockIdx.x * 8 + warp;
    if (row >= N) return;
    float s0 = 0.0f, s1 = 0.0f;
    #pragma unroll
    for (int k0 = 0; k0 < 96; k0 += 32) {
        int c = k0 + lane;
        float x = X[(size_t)row * 96 + c];
        x = fmaxf(fmaf(x, g_scale[c], g_shift[c]), 0.f);
        s0 += x * Ws[c * 2];
        s1 += x * Ws[c * 2 + 1];
    }
    #pragma unroll
    for (int o = 16; o; o >>= 1) {
        s0 += __shfl_down_sync(0xffffffffu, s0, o);
        s1 += __shfl_down_sync(0xffffffffu, s1, o);
    }
    if (lane == 0) { T[(size_t)row * 2] = s0; T[(size_t)row * 2 + 1] = s1; }
}

// final width-2 aggregation: out[i] = b4 + T[i]*dinv2[i] + sum_e norm*T[src]
__global__ __launch_bounds__(256) void k_aggf(
    const float* __restrict__ T, const float* __restrict__ b4,
    float* __restrict__ out, int N) {
    int gw   = (blockIdx.x * blockDim.x + threadIdx.x) >> 5;
    int lane = threadIdx.x & 31;
    if (gw >= N) return;
    int beg = g_offs[gw], end = g_offs[gw + 1];
    float a0 = 0.f, a1 = 0.f;
    for (int e = beg + lane; e < end; e += 32) {
        int2 ed = g_csr[e];
        float2 v = __ldg((const float2*)T + ed.x);
        float nm = __int_as_float(ed.y);
        a0 = fmaf(nm, v.x, a0);
        a1 = fmaf(nm, v.y, a1);
    }
    #pragma unroll
    for (int o = 16; o; o >>= 1) {
        a0 += __shfl_down_sync(0xffffffffu, a0, o);
        a1 += __shfl_down_sync(0xffffffffu, a1, o);
    }
    if (lane == 0) {
        float2 t = ((const float2*)T)[gw];
        float w = g_dinv2[gw];
        out[2 * gw]     = b4[0] + t.x * w + a0;
        out[2 * gw + 1] = b4[1] + t.y * w + a1;
    }
}

// ---------------- host ----------------
static inline int cdiv(int a, int b) { return (a + b - 1) / b; }

extern "C" void kernel_launch(void* const* d_in, const int* in_sizes, int n_in,
                              void* d_out, int out_size) {
    const float* x  = (const float*)d_in[0];
    const int*   ei = (const int*)d_in[1];
    const float* W1 = (const float*)d_in[2];  const float* b1 = (const float*)d_in[3];
    const float* g1 = (const float*)d_in[4];  const float* be1 = (const float*)d_in[5];
    const float* W2 = (const float*)d_in[6];  const float* b2 = (const float*)d_in[7];
    const float* g2 = (const float*)d_in[8];  const float* be2 = (const float*)d_in[9];
    const float* W3 = (const float*)d_in[10]; const float* b3 = (const float*)d_in[11];
    const float* g3 = (const float*)d_in[12]; const float* be3 = (const float*)d_in[13];
    const float* W4 = (const float*)d_in[14]; const float* b4 = (const float*)d_in[15];
    float* out = (float*)d_out;

    int E   = in_sizes[1] / 2;
    int H   = in_sizes[3];           // 96
    int Fin = in_sizes[2] / H;       // 32
    int N   = in_sizes[0] / Fin;     // 50000
    (void)n_in; (void)out_size;

    void *pA = nullptr, *pB = nullptr;
    cudaGetSymbolAddress(&pA, g_bufA);
    cudaGetSymbolAddress(&pB, g_bufB);
    float* bufA = (float*)pA;
    float* bufB = (float*)pB;

    int nb = cdiv(N, 256);

    // -------- per-call graph preprocessing: degrees, norms, CSR --------
    k_detect <<<1, 256>>>(ei);
    k_zerodeg<<<nb, 256>>>(N);
    k_count  <<<cdiv(E, 256), 256>>>(ei, E);
    k_dinv   <<<nb, 256>>>(N);
    k_bsum   <<<nb, 256>>>(N);
    k_bscan  <<<1, 512>>>(nb);
    k_offsets<<<nb, 256>>>(N);
    k_scatter<<<cdiv(E, 256), 256>>>(ei, E);

    dim3 gblk(16, 16);
    int aggGrid = cdiv(N, 8);   // 8 nodes (warps) per 256-thread block

    // -------- layer 1: aggregate x (w=32, no BN) -> gemm(+stats) -> bn coeffs --------
    k_agg<8, false><<<aggGrid, 256>>>(x, bufA, N);
    k_zstats<<<1, 96>>>();
    k_gemm96<<<cdiv(N, 32), gblk>>>(bufA, W1, b1, bufB, N, Fin);
    k_bnfin<<<1, 96>>>(g1, be1, N);

    // -------- layer 2: BN+ReLU fused into gather --------
    k_agg<24, true><<<aggGrid, 256>>>(bufB, bufA, N);
    k_zstats<<<1, 96>>>();
    k_gemm96<<<cdiv(N, 32), gblk>>>(bufA, W2, b2, bufB, N, 96);
    k_bnfin<<<1, 96>>>(g2, be2, N);

    // -------- layer 3 --------
    k_agg<24, true><<<aggGrid, 256>>>(bufB, bufA, N);
    k_zstats<<<1, 96>>>();
    k_gemm96<<<cdiv(N, 32), gblk>>>(bufA, W3, b3, bufB, N, 96);
    k_bnfin<<<1, 96>>>(g3, be3, N);

    // -------- layer 4: BN3+ReLU fused into projection, then gather w=2 --------
    k_gemm_out<<<cdiv(N, 8), 256>>>(bufB, W4, bufA, N);
    k_aggf<<<aggGrid, 256>>>(bufA, b4, out, N);
}

// round 3
// speedup vs baseline: 1.8211x; 1.1998x over previous
#include <cuda_runtime.h>
#include <cstdint>

// ---------------- static device scratch ----------------
#define MAXN 131072
#define MAXE 2000000

__device__ int    g_flag64;
__device__ int    g_deg[MAXN];
__device__ float  g_dinv[MAXN];
__device__ float  g_dinv2[MAXN];
__device__ int    g_offs[MAXN + 1];
__device__ int    g_cursor[MAXN];
__device__ int    g_bsum[MAXN / 256 + 2];
__device__ int    g_bpre[MAXN / 256 + 2];
__device__ int2   g_csr[MAXE];          // (src, norm-as-int)
__device__ float  g_bufA[(size_t)MAXN * 96];
__device__ float  g_bufB[(size_t)MAXN * 96];
__device__ double g_sum8[8][96];
__device__ double g_sq8[8][96];
__device__ float  g_scale[96];
__device__ float  g_shift[96];

// ---------------- init: dtype detect + zero degrees + zero stats ----------------
__global__ void k_init(const int* __restrict__ p, int N) {
    int i = blockIdx.x * blockDim.x + threadIdx.x;
    if (i < N) g_deg[i] = 0;
    if (i < 8 * 96) { ((double*)g_sum8)[i] = 0.0; ((double*)g_sq8)[i] = 0.0; }
    if (blockIdx.x == 0) {
        // int64 detection: high words of values < 2^31 are all zero
        int v = p[2 * threadIdx.x + 1];
        unsigned any = __ballot_sync(0xffffffffu, v != 0);
        __shared__ int s;
        if (threadIdx.x == 0) s = 0;
        __syncthreads();
        if (any && (threadIdx.x % 32 == 0)) atomicOr(&s, 1);
        __syncthreads();
        if (threadIdx.x == 0) g_flag64 = (s == 0) ? 1 : 0;
    }
}

__global__ void k_count(const int* __restrict__ p, int E) {
    int e = blockIdx.x * blockDim.x + threadIdx.x;
    if (e >= E) return;
    int d = g_flag64 ? p[2 * (E + e)] : p[E + e];
    atomicAdd(&g_deg[d], 1);
}

// dinv/dinv2 + per-block degree sums (fused)
__global__ void k_dinv_bsum(int N) {
    __shared__ int sh[256];
    int t = threadIdx.x;
    int i = blockIdx.x * 256 + t;
    int dg = (i < N) ? g_deg[i] : 0;
    if (i < N) {
        float dt = (float)(dg + 1);   // +1 self-loop
        g_dinv[i]  = rsqrtf(dt);
        g_dinv2[i] = 1.0f / dt;
    }
    sh[t] = dg;
    __syncthreads();
    for (int s = 128; s; s >>= 1) {
        if (t < s) sh[t] += sh[t + s];
        __syncthreads();
    }
    if (t == 0) g_bsum[blockIdx.x] = sh[0];
}

__global__ void k_bscan(int nb) {   // single block, 512 threads
    __shared__ int sh[512];
    int t = threadIdx.x;
    int v = (t < nb) ? g_bsum[t] : 0;
    sh[t] = v;
    __syncthreads();
    for (int o = 1; o < 512; o <<= 1) {
        int x = (t >= o) ? sh[t - o] : 0;
        __syncthreads();
        sh[t] += x;
        __syncthreads();
    }
    if (t < nb) g_bpre[t] = sh[t] - v;  // exclusive
}

__global__ void k_offsets(int N) {
    __shared__ int sh[256];
    int t = threadIdx.x;
    int i = blockIdx.x * 256 + t;
    int v = (i < N) ? g_deg[i] : 0;
    sh[t] = v;
    __syncthreads();
    for (int o = 1; o < 256; o <<= 1) {
        int x = (t >= o) ? sh[t - o] : 0;
        __syncthreads();
        sh[t] += x;
        __syncthreads();
    }
    if (i < N) {
        int off = g_bpre[blockIdx.x] + sh[t] - v;
        g_offs[i]   = off;
        g_cursor[i] = off;
        if (i == N - 1) g_offs[N] = off + v;
    }
}

__global__ void k_scatter(const int* __restrict__ p, int E) {
    int e = blockIdx.x * blockDim.x + threadIdx.x;
    if (e >= E) return;
    int s, d;
    if (g_flag64) { s = p[2 * e]; d = p[2 * (E + e)]; }
    else          { s = p[e];     d = p[E + e]; }
    int pos = atomicAdd(&g_cursor[d], 1);
    g_csr[pos] = make_int2(s, __float_as_int(g_dinv[s] * g_dinv[d]));
}

// ---------------- CSR gather aggregation (warp per node, no BN) ----------------
template<int NL>
__global__ __launch_bounds__(256) void k_agg(
    const float* __restrict__ h, float* __restrict__ out, int N) {
    int gw   = (blockIdx.x * blockDim.x + threadIdx.x) >> 5;
    int lane = threadIdx.x & 31;
    if (gw >= N) return;
    const float4* hp = (const float4*)h;
    bool act = lane < NL;
    float4 acc = make_float4(0, 0, 0, 0);
    if (act) {
        float4 v = __ldg(hp + (size_t)gw * NL + lane);
        float w = g_dinv2[gw];
        acc = make_float4(v.x * w, v.y * w, v.z * w, v.w * w);
    }
    int beg = g_offs[gw], end = g_offs[gw + 1];
    for (int e0 = beg; e0 < end; e0 += 32) {
        int e = e0 + lane;
        int2 ed = (e < end) ? g_csr[e] : make_int2(0, 0);
        int m = end - e0; if (m > 32) m = 32;
        int j = 0;
        for (; j + 2 <= m; j += 2) {
            int   s0 = __shfl_sync(0xffffffffu, ed.x, j);
            float n0 = __int_as_float(__shfl_sync(0xffffffffu, ed.y, j));
            int   s1 = __shfl_sync(0xffffffffu, ed.x, j + 1);
            float n1 = __int_as_float(__shfl_sync(0xffffffffu, ed.y, j + 1));
            if (act) {
                float4 v0 = __ldg(hp + (size_t)s0 * NL + lane);
                float4 v1 = __ldg(hp + (size_t)s1 * NL + lane);
                acc.x = fmaf(n0, v0.x, acc.x); acc.y = fmaf(n0, v0.y, acc.y);
                acc.z = fmaf(n0, v0.z, acc.z); acc.w = fmaf(n0, v0.w, acc.w);
                acc.x = fmaf(n1, v1.x, acc.x); acc.y = fmaf(n1, v1.y, acc.y);
                acc.z = fmaf(n1, v1.z, acc.z); acc.w = fmaf(n1, v1.w, acc.w);
            }
        }
        if (j < m) {
            int   s0 = __shfl_sync(0xffffffffu, ed.x, j);
            float n0 = __int_as_float(__shfl_sync(0xffffffffu, ed.y, j));
            if (act) {
                float4 v0 = __ldg(hp + (size_t)s0 * NL + lane);
                acc.x = fmaf(n0, v0.x, acc.x); acc.y = fmaf(n0, v0.y, acc.y);
                acc.z = fmaf(n0, v0.z, acc.z); acc.w = fmaf(n0, v0.w, acc.w);
            }
        }
    }
    if (act) ((float4*)out)[(size_t)gw * NL + lane] = acc;
}

// ---------------- GEMM: Y[N,96] = X[N,Fi] @ W[Fi,96] + b, FFMA2, fused BN stats ----------------
// 32 rows x 96 cols per block; thread tile 2 rows x 6 cols (packed f32x2 math)
__global__ __launch_bounds__(256) void k_gemm96(
    const float* __restrict__ X, const float* __restrict__ W,
    const float* __restrict__ b, float* __restrict__ Y, int N, int Fi) {
    __shared__ float Ws[96 * 96];
    __shared__ float Xt[96 * 32];   // transposed tile; reused as stats buffer
    int tid = threadIdx.x;
    int tx = tid & 15, ty = tid >> 4;
    for (int i = tid; i < Fi * 96; i += 256) Ws[i] = W[i];
    int row0 = blockIdx.x * 32;
    for (int i = tid; i < 32 * Fi; i += 256) {
        int r = i & 31, k = i >> 5;
        int row = row0 + r;
        Xt[k * 32 + r] = (row < N) ? X[(size_t)row * Fi + k] : 0.0f;
    }
    __syncthreads();

    unsigned long long acc[2][3] = {{0, 0, 0}, {0, 0, 0}};
    int cb = ty * 6;
    #pragma unroll 4
    for (int k = 0; k < Fi; k++) {
        float2 a2 = *(const float2*)&Xt[k * 32 + 2 * tx];
        unsigned long long p0, p1;
        asm("mov.b64 %0, {%1, %1};" : "=l"(p0) : "f"(a2.x));
        asm("mov.b64 %0, {%1, %1};" : "=l"(p1) : "f"(a2.y));
        const unsigned long long* wrow = (const unsigned long long*)&Ws[k * 96 + cb];
        #pragma unroll
        for (int p = 0; p < 3; p++) {
            unsigned long long w2 = wrow[p];
            asm("fma.rn.f32x2 %0, %1, %2, %0;" : "+l"(acc[0][p]) : "l"(p0), "l"(w2));
            asm("fma.rn.f32x2 %0, %1, %2, %0;" : "+l"(acc[1][p]) : "l"(p1), "l"(w2));
        }
    }

    float bb[6];
    #pragma unroll
    for (int j = 0; j < 6; j++) bb[j] = b[cb + j];
    float ls[6] = {0, 0, 0, 0, 0, 0}, lq[6] = {0, 0, 0, 0, 0, 0};
    #pragma unroll
    for (int rr = 0; rr < 2; rr++) {
        int row = row0 + 2 * tx + rr;
        if (row < N) {
            float v[6];
            #pragma unroll
            for (int p = 0; p < 3; p++)
                asm("mov.b64 {%0, %1}, %2;" : "=f"(v[2 * p]), "=f"(v[2 * p + 1]) : "l"(acc[rr][p]));
            #pragma unroll
            for (int j = 0; j < 6; j++) {
                float val = v[j] + bb[j];
                v[j] = val;
                ls[j] += val; lq[j] += val * val;
            }
            float2* yp = (float2*)&Y[(size_t)row * 96 + cb];
            yp[0] = make_float2(v[0], v[1]);
            yp[1] = make_float2(v[2], v[3]);
            yp[2] = make_float2(v[4], v[5]);
        }
    }

    // stats reduction over the 16 tx slots per column (pad 102 -> conflict-free)
    __syncthreads();
    float* sr = Xt;
    int sh = blockIdx.x & 7;
    #pragma unroll
    for (int j = 0; j < 6; j++) sr[tx * 102 + cb + j] = ls[j];
    __syncthreads();
    for (int st = 8; st; st >>= 1) {
        if (tx < st)
            #pragma unroll
            for (int j = 0; j < 6; j++)
                sr[tx * 102 + cb + j] += sr[(tx + st) * 102 + cb + j];
        __syncthreads();
    }
    if (tx == 0)
        #pragma unroll
        for (int j = 0; j < 6; j++) atomicAdd(&g_sum8[sh][cb + j], (double)sr[cb + j]);
    __syncthreads();
    #pragma unroll
    for (int j = 0; j < 6; j++) sr[tx * 102 + cb + j] = lq[j];
    __syncthreads();
    for (int st = 8; st; st >>= 1) {
        if (tx < st)
            #pragma unroll
            for (int j = 0; j < 6; j++)
                sr[tx * 102 + cb + j] += sr[(tx + st) * 102 + cb + j];
        __syncthreads();
    }
    if (tx == 0)
        #pragma unroll
        for (int j = 0; j < 6; j++) atomicAdd(&g_sq8[sh][cb + j], (double)sr[cb + j]);
}

// finalize BN coefficients, then zero the shadow accumulators for the next layer
__global__ void k_bnfin(const float* __restrict__ g, const float* __restrict__ be, int N) {
    int c = threadIdx.x;
    if (c >= 96) return;
    double s = 0.0, q = 0.0;
    #pragma unroll
    for (int i = 0; i < 8; i++) { s += g_sum8[i][c]; q += g_sq8[i][c]; }
    double mu  = s / (double)N;
    double var = q / (double)N - mu * mu;
    if (var < 0.0) var = 0.0;
    float a = g[c] * rsqrtf((float)var + 1e-5f);
    g_scale[c] = a;
    g_shift[c] = be[c] - (float)mu * a;
    #pragma unroll
    for (int i = 0; i < 8; i++) { g_sum8[i][c] = 0.0; g_sq8[i][c] = 0.0; }
}

// elementwise BN+ReLU (applied once per node, not per edge)
__global__ void k_bnrelu(const float* __restrict__ X, float* __restrict__ Y, int total4) {
    int t = blockIdx.x * blockDim.x + threadIdx.x;
    if (t >= total4) return;
    int c = t % 24;
    float4 sc = ((const float4*)g_scale)[c];
    float4 sf = ((const float4*)g_shift)[c];
    float4 v = ((const float4*)X)[t];
    v.x = fmaxf(fmaf(v.x, sc.x, sf.x), 0.f);
    v.y = fmaxf(fmaf(v.y, sc.y, sf.y), 0.f);
    v.z = fmaxf(fmaf(v.z, sc.z, sf.z), 0.f);
    v.w = fmaxf(fmaf(v.w, sc.w, sf.w), 0.f);
    ((float4*)Y)[t] = v;
}

// ---------------- final projection with fused BN3+ReLU: T[N,2] ----------------
__global__ __launch_bounds__(256) void k_gemm_out(
    const float* __restrict__ X, const float* __restrict__ W,
    float* __restrict__ T, int N) {
    __shared__ float Ws[192];
    int tid = threadIdx.x;
    if (tid < 192) Ws[tid] = W[tid];
    __syncthreads();
    int warp = tid / 32, lane = tid % 32;
    int row = blockIdx.x * 8 + warp;
    if (row >= N) return;
    float s0 = 0.0f, s1 = 0.0f;
    #pragma unroll
    for (int k0 = 0; k0 < 96; k0 += 32) {
        int c = k0 + lane;
        float x = X[(size_t)row * 96 + c];
        x = fmaxf(fmaf(x, g_scale[c], g_shift[c]), 0.f);
        s0 += x * Ws[c * 2];
        s1 += x * Ws[c * 2 + 1];
    }
    #pragma unroll
    for (int o = 16; o; o >>= 1) {
        s0 += __shfl_down_sync(0xffffffffu, s0, o);
        s1 += __shfl_down_sync(0xffffffffu, s1, o);
    }
    if (lane == 0) { T[(size_t)row * 2] = s0; T[(size_t)row * 2 + 1] = s1; }
}

// final width-2 aggregation: out[i] = b4 + T[i]*dinv2[i] + sum_e norm*T[src]
__global__ __launch_bounds__(256) void k_aggf(
    const float* __restrict__ T, const float* __restrict__ b4,
    float* __restrict__ out, int N) {
    int gw   = (blockIdx.x * blockDim.x + threadIdx.x) >> 5;
    int lane = threadIdx.x & 31;
    if (gw >= N) return;
    int beg = g_offs[gw], end = g_offs[gw + 1];
    float a0 = 0.f, a1 = 0.f;
    for (int e = beg + lane; e < end; e += 32) {
        int2 ed = g_csr[e];
        float2 v = __ldg((const float2*)T + ed.x);
        float nm = __int_as_float(ed.y);
        a0 = fmaf(nm, v.x, a0);
        a1 = fmaf(nm, v.y, a1);
    }
    #pragma unroll
    for (int o = 16; o; o >>= 1) {
        a0 += __shfl_down_sync(0xffffffffu, a0, o);
        a1 += __shfl_down_sync(0xffffffffu, a1, o);
    }
    if (lane == 0) {
        float2 t = ((const float2*)T)[gw];
        float w = g_dinv2[gw];
        out[2 * gw]     = b4[0] + t.x * w + a0;
        out[2 * gw + 1] = b4[1] + t.y * w + a1;
    }
}

// ---------------- host ----------------
static inline int cdiv(int a, int b) { return (a + b - 1) / b; }

extern "C" void kernel_launch(void* const* d_in, const int* in_sizes, int n_in,
                              void* d_out, int out_size) {
    const float* x  = (const float*)d_in[0];
    const int*   ei = (const int*)d_in[1];
    const float* W1 = (const float*)d_in[2];  const float* b1 = (const float*)d_in[3];
    const float* g1 = (const float*)d_in[4];  const float* be1 = (const float*)d_in[5];
    const float* W2 = (const float*)d_in[6];  const float* b2 = (const float*)d_in[7];
    const float* g2 = (const float*)d_in[8];  const float* be2 = (const float*)d_in[9];
    const float* W3 = (const float*)d_in[10]; const float* b3 = (const float*)d_in[11];
    const float* g3 = (const float*)d_in[12]; const float* be3 = (const float*)d_in[13];
    const float* W4 = (const float*)d_in[14]; const float* b4 = (const float*)d_in[15];
    float* out = (float*)d_out;

    int E   = in_sizes[1] / 2;
    int H   = in_sizes[3];           // 96
    int Fin = in_sizes[2] / H;       // 32
    int N   = in_sizes[0] / Fin;     // 50000
    (void)n_in; (void)out_size;

    void *pA = nullptr, *pB = nullptr;
    cudaGetSymbolAddress(&pA, g_bufA);
    cudaGetSymbolAddress(&pB, g_bufB);
    float* bufA = (float*)pA;
    float* bufB = (float*)pB;

    int nb = cdiv(N, 256);
    int gemmGrid = cdiv(N, 32);
    int aggGrid  = cdiv(N, 8);   // 8 nodes (warps) per 256-thread block

    // -------- per-call graph preprocessing: degrees, norms, CSR --------
    k_init     <<<nb, 256>>>(ei, N);
    k_count    <<<cdiv(E, 256), 256>>>(ei, E);
    k_dinv_bsum<<<nb, 256>>>(N);
    k_bscan    <<<1, 512>>>(nb);
    k_offsets  <<<nb, 256>>>(N);
    k_scatter  <<<cdiv(E, 256), 256>>>(ei, E);

    // -------- layer 1: aggregate x (w=32) -> gemm(+stats) -> bnfin -> bnrelu --------
    k_agg<8><<<aggGrid, 256>>>(x, bufA, N);
    k_gemm96<<<gemmGrid, 256>>>(bufA, W1, b1, bufB, N, Fin);
    k_bnfin<<<1, 96>>>(g1, be1, N);
    k_bnrelu<<<cdiv(N * 24, 256), 256>>>(bufB, bufB, N * 24);

    // -------- layer 2 --------
    k_agg<24><<<aggGrid, 256>>>(bufB, bufA, N);
    k_gemm96<<<gemmGrid, 256>>>(bufA, W2, b2, bufB, N, 96);
    k_bnfin<<<1, 96>>>(g2, be2, N);
    k_bnrelu<<<cdiv(N * 24, 256), 256>>>(bufB, bufB, N * 24);

    // -------- layer 3 --------
    k_agg<24><<<aggGrid, 256>>>(bufB, bufA, N);
    k_gemm96<<<gemmGrid, 256>>>(bufA, W3, b3, bufB, N, 96);
    k_bnfin<<<1, 96>>>(g3, be3, N);

    // -------- layer 4: BN3+ReLU fused into projection, then gather w=2 --------
    k_gemm_out<<<cdiv(N, 8), 256>>>(bufB, W4, bufA, N);
    k_aggf<<<aggGrid, 256>>>(bufA, b4, out, N);
}